// round 13
// baseline (speedup 1.0000x reference)
#include <cuda_runtime.h>
#include <cuda_bf16.h>
#include <stdint.h>

#define BUCKET_SIZE 512
#define G1    296               // blocks for pass1 / rank pass
#define WPB   8                 // warps per block
#define W     (G1 * WPB)        // 2368 warp-tiles
#define MAXNBP 8192             // padded bucket-row stride (actual nbp = 7824)
#define MAXN  4194304

// Scratch (static; no allocations)
__device__ unsigned char  g_cnt8  [(size_t)W * MAXNBP];          // 19.4MB per-warp-tile counts
__device__ unsigned short g_base16[(size_t)W * MAXNBP];          // 38.8MB clamped absolute bases
__device__ unsigned       g_part  [(size_t)G1 * MAXNBP];         //  9.7MB per-block sums -> bases
__device__ unsigned short g_bkt   [MAXN];                        //  8MB per-point bucket
__device__ unsigned       g_cnt   [MAXNBP];                      // per-bucket totals
__device__ unsigned       g_inv   [(size_t)MAXNBP * BUCKET_SIZE];// 16MB slot -> point idx

// ---- Pass 1: hash + warp-private u8 counting; epilogue emits per-block sums ----
__global__ __launch_bounds__(256) void psh_pass1(
    const float* __restrict__ coords, const int* __restrict__ seps,
    const int* __restrict__ hop_p, int n, int nB, int nb, int nbp, int wtile,
    unsigned long long magic_nb, float* __restrict__ out_bucket)
{
    extern __shared__ unsigned char cnt[];   // [WPB][nbp]
    const int lane = threadIdx.x & 31;
    const int wid  = threadIdx.x >> 5;
    const int nq   = nbp >> 2;
    for (int j = threadIdx.x; j < WPB * nq; j += 256)
        ((unsigned*)cnt)[j] = 0u;
    __syncthreads();
    unsigned char* cw = cnt + wid * nbp;

    const unsigned hop = (unsigned)hop_p[0];
    const int wt  = blockIdx.x * WPB + wid;
    const int beg = wt * wtile;
    const int end = min(n, beg + wtile);

    int klo = 0, khi = 0;
    if (beg < end) {
        for (int k = 0; k < nB; k++) {
            int s = __ldg(&seps[k]);
            klo += (s <= beg);
            khi += (s <= end - 1);
        }
    }

    int i = beg + lane;
    bool v = (i < end);
    float x = 0.f, y = 0.f, z = 0.f;
    if (v) { x = coords[3*i]; y = coords[3*i+1]; z = coords[3*i+2]; }

    for (int c = beg; c < end; c += 32) {
        int ni = i + 32;                       // prefetch next chunk
        bool vn = (ni < end);
        float nx = 0.f, ny = 0.f, nz = 0.f;
        if (vn) { nx = coords[3*ni]; ny = coords[3*ni+1]; nz = coords[3*ni+2]; }

        unsigned vm = __ballot_sync(0xffffffffu, v);
        if (v) {
            unsigned bid = (unsigned)klo;
            for (int k = klo; k < khi; k++) bid += (__ldg(&seps[k]) <= i);
            unsigned vx = (unsigned)(int)floorf(x);
            unsigned vy = (unsigned)(int)floorf(y);
            unsigned vz = (unsigned)(int)floorf(z);
            unsigned h = vx * 73856093u ^ vy * 19349663u ^ vz * 83492791u
                       ^ bid * 2654435761u;
            h += hop;
            unsigned q = (unsigned)__umul64hi((unsigned long long)h, magic_nb);
            unsigned b = h - q * (unsigned)nb;
            out_bucket[i] = (float)b;
            g_bkt[i] = (unsigned short)b;
            unsigned mask = __match_any_sync(vm, b);
            if (lane == __ffs(mask) - 1)
                cw[b] = (unsigned char)(cw[b] + __popc(mask));
        }
        i = ni; v = vn; x = nx; y = ny; z = nz;
    }

    // per-warp raw row flush (coalesced u32; own data, warp-sync only)
    __syncwarp();
    {
        const unsigned* src = (const unsigned*)(cnt + wid * nbp);
        unsigned* dst = (unsigned*)(g_cnt8 + (size_t)wt * nbp);
        for (int j = lane; j < nq; j += 32) dst[j] = src[j];
    }

    // fused 2a: per-block sums (byte-SIMD over 8 warp rows; each byte sum < 256)
    __syncthreads();
    unsigned* bp = g_part + (size_t)blockIdx.x * nbp;
    for (int q = threadIdx.x; q < nq; q += 256) {
        unsigned s = 0;
        #pragma unroll
        for (int w = 0; w < WPB; w++)
            s += ((const unsigned*)cnt)[w * nq + q];
        uint4 pk;
        pk.x = s & 255u;          pk.y = (s >> 8) & 255u;
        pk.z = (s >> 16) & 255u;  pk.w = s >> 24;
        *(uint4*)(bp + q * 4) = pk;
    }
}

// ---- Scan 2b: exclusive scan of 296 block sums per bucket; emit counts ----
__global__ __launch_bounds__(256) void psh_pass2b(
    int nb, int nbp, float* __restrict__ out_counts)
{
    int j = blockIdx.x * 256 + threadIdx.x;
    if (j >= nbp) return;
    unsigned carry = 0;
    #pragma unroll 8
    for (int blk = 0; blk < G1; blk++) {
        size_t o = (size_t)blk * nbp + j;
        unsigned v = g_part[o];
        g_part[o] = carry;
        carry += v;
    }
    if (j < nb) {
        g_cnt[j] = carry;
        out_counts[j] = (float)carry;
    }
}

// ---- Scan 2c: 8-row rescan per block -> clamped u16 absolute bases ----
__global__ __launch_bounds__(256) void psh_pass2c(int nbp)
{
    const int nq = nbp >> 2;
    int q   = blockIdx.x * 256 + threadIdx.x;
    int blk = blockIdx.y;
    if (q >= nq) return;
    size_t o = (size_t)blk * nbp + q * 4;
    uint4 av = *(const uint4*)(g_part + o);
    unsigned a0 = av.x, a1 = av.y, a2 = av.z, a3 = av.w;
    const unsigned* rows = (const unsigned*)g_cnt8;
    const int wt0 = blk * WPB;
    #pragma unroll
    for (int w = 0; w < WPB; w++) {
        uint2 pk;
        pk.x = min(a0, 1024u) | (min(a1, 1024u) << 16);
        pk.y = min(a2, 1024u) | (min(a3, 1024u) << 16);
        *(uint2*)(g_base16 + (size_t)(wt0 + w) * nbp + q * 4) = pk;
        unsigned vv = rows[(size_t)(wt0 + w) * nq + q];
        a0 += vv & 255u;         a1 += (vv >> 8) & 255u;
        a2 += (vv >> 16) & 255u; a3 += vv >> 24;
    }
}

// ---- Rank pass: warp-private u8 counters + prefetched base; emit inv (4B, L2-hot) ----
__global__ __launch_bounds__(256) void psh_rank(int n, int nbp, int wtile)
{
    extern __shared__ unsigned char cnt[];   // [WPB][nbp]
    const int lane = threadIdx.x & 31;
    const int wid  = threadIdx.x >> 5;
    for (int j = threadIdx.x; j < (WPB * nbp) >> 2; j += 256)
        ((unsigned*)cnt)[j] = 0u;
    __syncthreads();
    unsigned char* cw = cnt + wid * nbp;

    const int wt  = blockIdx.x * WPB + wid;
    const int beg = wt * wtile;
    const int end = min(n, beg + wtile);
    const unsigned short* baserow = g_base16 + (size_t)wt * nbp;

    int i = beg + lane;
    bool v = (i < end);
    unsigned b    = v ? (unsigned)g_bkt[i] : 0u;
    unsigned base = v ? (unsigned)__ldg(&baserow[b]) : 0u;

    for (int c = beg; c < end; c += 32) {
        int ni = i + 32;                      // prefetch next chunk (bkt + base)
        bool vn = (ni < end);
        unsigned bn    = vn ? (unsigned)g_bkt[ni] : 0u;
        unsigned basen = vn ? (unsigned)__ldg(&baserow[bn]) : 0u;

        unsigned vm = __ballot_sync(0xffffffffu, v);
        if (v) {
            unsigned mask = __match_any_sync(vm, b);
            int leader = __ffs(mask) - 1;
            unsigned local = 0;
            if (lane == leader) {
                local = cw[b];
                cw[b] = (unsigned char)(local + __popc(mask));
            }
            local = __shfl_sync(mask, local, leader);
            unsigned rank = base + local + __popc(mask & ((1u << lane) - 1u));
            if (rank < BUCKET_SIZE)
                g_inv[(size_t)b * BUCKET_SIZE + rank] = (unsigned)i;
        }
        i = ni; v = vn; b = bn; base = basen;
    }
}

// ---- Pass 4: gather, 4 CONSECUTIVE slots/thread (uint4 inv, float4 stores) ----
__global__ __launch_bounds__(256) void psh_pass4(
    const float* __restrict__ coords, int pad_to,
    float* __restrict__ out_coord)
{
    int s0 = (blockIdx.x * 256 + threadIdx.x) * 4;
    if (s0 >= pad_to) return;
    int b  = s0 >> 9;                         // all 4 slots in same bucket (4 | 512)
    int r0 = s0 & (BUCKET_SIZE - 1);
    unsigned cb = g_cnt[b];
    uint4 iv = *(const uint4*)(g_inv + s0);
    unsigned id[4] = {iv.x, iv.y, iv.z, iv.w};
    float o[12];
    #pragma unroll
    for (int k = 0; k < 4; k++) {
        bool val = (unsigned)(r0 + k) < cb;
        o[3*k+0] = val ? __ldg(&coords[3 * id[k]    ]) : 0.f;
        o[3*k+1] = val ? __ldg(&coords[3 * id[k] + 1]) : 0.f;
        o[3*k+2] = val ? __ldg(&coords[3 * id[k] + 2]) : 0.f;
    }
    float4* dst = (float4*)(out_coord + (size_t)s0 * 3);
    dst[0] = make_float4(o[0], o[1], o[2],  o[3]);
    dst[1] = make_float4(o[4], o[5], o[6],  o[7]);
    dst[2] = make_float4(o[8], o[9], o[10], o[11]);
}

extern "C" void kernel_launch(void* const* d_in, const int* in_sizes, int n_in,
                              void* d_out, int out_size)
{
    const float* coords = (const float*)d_in[0];
    const int*   seps   = (const int*)d_in[1];
    const int*   hop_p  = (const int*)d_in[2];

    const int n  = in_sizes[0] / 3;
    const int nB = in_sizes[1];
    const int pad_to = ((n + BUCKET_SIZE - 1) / BUCKET_SIZE) * BUCKET_SIZE;
    const int nb  = pad_to / BUCKET_SIZE;
    const int nbp = (nb + 7) & ~7;           // padded row stride (mult of 8)
    const int wtile = (n + W - 1) / W;       // 1690 for n=4M

    float* out_coord  = (float*)d_out;
    float* out_counts = out_coord + (size_t)pad_to * 3;
    float* out_bucket = out_counts + nb;

    unsigned long long magic_nb = (~0ULL) / (unsigned)nb + 1ULL;

    size_t shw = (size_t)WPB * nbp;          // ~62.5 KB -> 3 blocks/SM

    static bool attr_set = false;
    if (!attr_set) {
        cudaFuncSetAttribute(psh_pass1,
                             cudaFuncAttributeMaxDynamicSharedMemorySize,
                             WPB * MAXNBP);
        cudaFuncSetAttribute(psh_rank,
                             cudaFuncAttributeMaxDynamicSharedMemorySize,
                             WPB * MAXNBP);
        attr_set = true;
    }

    const int nq = nbp >> 2;
    dim3 g2c((nq + 255) / 256, G1);
    psh_pass1<<<G1, 256, shw>>>(coords, seps, hop_p, n, nB, nb, nbp, wtile,
                                magic_nb, out_bucket);
    psh_pass2b<<<(nbp + 255) / 256, 256>>>(nb, nbp, out_counts);
    psh_pass2c<<<g2c, 256>>>(nbp);
    psh_rank<<<G1, 256, shw>>>(n, nbp, wtile);
    psh_pass4<<<(pad_to / 4 + 255) / 256, 256>>>(coords, pad_to, out_coord);
}